// round 12
// baseline (speedup 1.0000x reference)
#include <cuda_runtime.h>
#include <cstdint>

// ---------------- problem constants ----------------
#define NCC   29
#define NIMG  3
#define NHID  16
#define NOUT  10
#define B_    16
#define HW_   64
#define PIX   4096           // 64*64
#define INVEC 88             // 3*29+1
#define NT    512            // threads per CTA

typedef unsigned long long u64;

// ---------------- packed f32x2 helpers (bit-exact vs scalar FP32) ----------
__device__ __forceinline__ u64 bcast2(float a) {
    u64 r; asm("mov.b64 %0, {%1, %1};" : "=l"(r) : "f"(a)); return r;
}
__device__ __forceinline__ void unpack2(u64 v, float& a, float& b) {
    asm("mov.b64 {%0, %1}, %2;" : "=f"(a), "=f"(b) : "l"(v));
}
__device__ __forceinline__ u64 ffma2(u64 a, u64 b, u64 c) {
    u64 d; asm("fma.rn.f32x2 %0, %1, %2, %3;" : "=l"(d) : "l"(a), "l"(b), "l"(c));
    return d;
}

// ---------------- persistent device buffers (no allocation allowed) ----------
__device__ float g_bufA[B_ * NCC * PIX];
__device__ float g_bufB[B_ * NCC * PIX];
__device__ float g_w1t[96 * 256];    // [k(pad 96)][o=256]
__device__ float g_w2t[256 * 128];   // [k=256][o=128]
__device__ float g_w3t[128 * 32];    // [k=128][o(pad 32)]

// ---------------- JAX threefry2x32 (bit exact) ----------------
__device__ __forceinline__ void tf2x32(unsigned k0, unsigned k1,
                                       unsigned x0, unsigned x1,
                                       unsigned& o0, unsigned& o1) {
    unsigned ks2 = k0 ^ k1 ^ 0x1BD11BDAu;
    x0 += k0; x1 += k1;
#define TFR(r) { x0 += x1; x1 = (x1 << (r)) | (x1 >> (32 - (r))); x1 ^= x0; }
    TFR(13) TFR(15) TFR(26) TFR(6)
    x0 += k1;  x1 += ks2 + 1u;
    TFR(17) TFR(29) TFR(16) TFR(24)
    x0 += ks2; x1 += k0 + 2u;
    TFR(13) TFR(15) TFR(26) TFR(6)
    x0 += k0;  x1 += k1 + 3u;
    TFR(17) TFR(29) TFR(16) TFR(24)
    x0 += k1;  x1 += ks2 + 4u;
    TFR(13) TFR(15) TFR(26) TFR(6)
    x0 += ks2; x1 += k0 + 5u;
#undef TFR
    o0 = x0; o1 = x1;
}

// XLA ErfInv32 (Giles polynomials) — matches jax.random.normal
__device__ __forceinline__ float erfinv_xla(float x) {
    float w = -log1pf(-x * x);
    float p;
    if (w < 5.0f) {
        w -= 2.5f;
        p = 2.81022636e-08f;
        p = fmaf(p, w, 3.43273939e-07f);
        p = fmaf(p, w, -3.5233877e-06f);
        p = fmaf(p, w, -4.39150654e-06f);
        p = fmaf(p, w, 0.00021858087f);
        p = fmaf(p, w, -0.00125372503f);
        p = fmaf(p, w, -0.00417768164f);
        p = fmaf(p, w, 0.246640727f);
        p = fmaf(p, w, 1.50140941f);
    } else {
        w = sqrtf(w) - 3.0f;
        p = -0.000200214257f;
        p = fmaf(p, w, 0.000100950558f);
        p = fmaf(p, w, 0.00134934322f);
        p = fmaf(p, w, -0.00367342844f);
        p = fmaf(p, w, 0.00573950773f);
        p = fmaf(p, w, -0.0076224613f);
        p = fmaf(p, w, 0.00943887047f);
        p = fmaf(p, w, 1.00167406f);
        p = fmaf(p, w, 2.83297682f);
    }
    return p * x;
}

__device__ __forceinline__ float lk(float v) { return v >= 0.0f ? v : 0.01f * v; }

// u in [0,1) from raw bits, JAX convention
__device__ __forceinline__ float bits_to_unit(unsigned bits) {
    return __uint_as_float((bits >> 9) | 0x3f800000u) - 1.0f;
}

// ---------------- init kernel: state = [x | hid | zeros] ----------------
__global__ void nca_init(const float* __restrict__ x) {
    long long idx = (long long)blockIdx.x * blockDim.x + threadIdx.x;
    const long long N = (long long)B_ * NCC * PIX;
    if (idx >= N) return;
    int p  = (int)(idx & (PIX - 1));
    int ch = (int)((idx >> 12) % NCC);
    int b  = (int)(idx / ((long long)NCC * PIX));
    float v;
    if (ch < NIMG) {
        v = x[((long long)b * NIMG + ch) * PIX + p];
    } else if (ch < NIMG + NHID) {
        unsigned kh0, kh1;
        tf2x32(0u, 42u, 0u, 10000u, kh0, kh1);
        unsigned ih = ((unsigned)b * NHID + (unsigned)(ch - NIMG)) * PIX + (unsigned)p;
        const unsigned half = 524288u;
        unsigned c0, c1, o0, o1, bits;
        if (ih < half) { c0 = ih; c1 = ih + half; }
        else           { c0 = ih - half; c1 = ih; }
        tf2x32(kh0, kh1, c0, c1, o0, o1);
        bits = (ih < half) ? o0 : o1;
        float u = bits_to_unit(bits);
        const float lo = -0.99999994f;           // nextafterf(-1,0)
        float val = u * (1.0f - lo) + lo;
        val = fmaxf(lo, val);
        float nrm = 1.41421356237f * erfinv_xla(val);   // sqrt(2)*erfinv
        v = 0.5f + 0.225f * nrm;
    } else {
        v = 0.0f;
    }
    g_bufA[idx] = v;
}

// ---------------- weight transpose / pad kernel ----------------
__global__ void nca_prep(const float* __restrict__ w1,
                         const float* __restrict__ w2,
                         const float* __restrict__ w3) {
    int i = blockIdx.x * blockDim.x + threadIdx.x;
    if (i < 96 * 256) {
        int k = i >> 8, o = i & 255;
        g_w1t[i] = (k < INVEC) ? w1[o * INVEC + k] : 0.0f;
    } else if (i < 96 * 256 + 256 * 128) {
        int j = i - 96 * 256;
        int k = j >> 7, o = j & 127;
        g_w2t[j] = w2[o * 256 + k];
    } else if (i < 96 * 256 + 256 * 128 + 128 * 32) {
        int j = i - 96 * 256 - 256 * 128;
        int k = j >> 5, o = j & 31;
        g_w3t[j] = (o < NCC) ? w3[o * 128 + k] : 0.0f;
    }
}

// ---------------- shared memory layout (floats) ----------------
#define S_SROWS 0                 // 29*3*66 = 5742 -> pad 5744
#define S_PERCS 5744              // 96*68   = 6528
#define S_H1    12272             // 256*68  = 17408
#define S_H2    29680             // 128*68  = 8704
#define S_WB    38384             // 32*256  = 8192 (max weight chunk)
#define S_FIRE  46576             // 64
#define S_TOTAL 46640
#define SMEM_BYTES (S_TOTAL * 4)

// ---------------- fused step kernel: one CTA per (b, row), 512 threads ------
__global__ __launch_bounds__(NT, 1)
void nca_step(int parity, int step, const int* __restrict__ steps_p,
              const float* __restrict__ b1) {
    extern __shared__ float sm[];
    float* srows = sm + S_SROWS;
    float* percs = sm + S_PERCS;
    float* h1s   = sm + S_H1;
    float* h2s   = sm + S_H2;
    float* wbuf  = sm + S_WB;
    float* fires = sm + S_FIRE;

    const int tid = threadIdx.x;
    const int bid = blockIdx.x;
    const int b = bid >> 6;
    const int h = bid & 63;
    const int tx = tid & 15;
    const int ty = tid >> 4;          // 0..31

    const float* sin_ = parity ? g_bufB : g_bufA;
    float*       sout = parity ? g_bufA : g_bufB;
    const float* base_in  = sin_ + ((long long)b * NCC) * PIX + h * 64;
    float*       base_out = sout + ((long long)b * NCC) * PIX + h * 64;

    const int S = steps_p ? steps_p[0] : 20;
    if (step >= S) {   // pass-through keeps double-buffer parity valid
        for (int i = tid; i < NCC * 64; i += NT) {
            int ch = i >> 6, w = i & 63;
            base_out[ch * PIX + w] = base_in[ch * PIX + w];
        }
        return;
    }

    // ---- stage 3 state rows (29ch x 3 x 66, zero-padded) ----
    for (int i = tid; i < NCC * 3 * 66; i += NT) {
        int ch = i / 198;
        int rem = i - ch * 198;
        int r = rem / 66;
        int c = rem - r * 66;
        int hh = h + r - 1;
        int ww = c - 1;
        float v = 0.0f;
        if (hh >= 0 && hh < 64 && ww >= 0 && ww < 64)
            v = sin_[((long long)b * NCC + ch) * PIX + hh * 64 + ww];
        srows[i] = v;
    }

    // ---- fire mask for this row (bit-exact JAX uniform < 0.5) ----
    if (tid < 64) {
        unsigned kf0, kf1;
        tf2x32(0u, 42u, 0u, (unsigned)step, kf0, kf1);   // fold_in(key(42), step)
        unsigned pix = ((unsigned)b * 64u + (unsigned)h) * 64u + (unsigned)tid;
        const unsigned half = 32768u;                    // n = 65536
        unsigned c0, c1, o0, o1;
        if (pix < half) { c0 = pix; c1 = pix + half; }
        else            { c0 = pix - half; c1 = pix; }
        tf2x32(kf0, kf1, c0, c1, o0, o1);
        unsigned bits = (pix < half) ? o0 : o1;
        float u = bits_to_unit(bits);
        fires[tid] = (u < 0.5f) ? 1.0f : 0.0f;
    }

    // ---- time channel + zero-pad rows 88..95 ----
    float tval = (float)step / 100.0f;
    if (tid < 68) percs[87 * 68 + tid] = (tid < 64) ? tval : 0.0f;
    for (int i = tid; i < 8 * 68; i += NT) percs[88 * 68 + i] = 0.0f;
    __syncthreads();

    // ---- perception: s, sobel-x, sobel-y ----
    for (int i = tid; i < NCC * 64; i += NT) {
        int ch = i >> 6, w = i & 63;
        const float* rp = srows + ch * 198;
        float tl = rp[w],       tc = rp[w + 1],       tr = rp[w + 2];
        float ml = rp[66 + w],                        mr = rp[66 + w + 2];
        float mc = rp[66 + w + 1];
        float bl = rp[132 + w], bc = rp[132 + w + 1], br = rp[132 + w + 2];
        float sx = ((tr - tl) + 2.0f * (mr - ml) + (br - bl)) * 0.125f;
        float sy = ((bl - tl) + 2.0f * (bc - tc) + (br - tr)) * 0.125f;
        percs[ch * 68 + w]        = mc;
        percs[(29 + ch) * 68 + w] = sx;
        percs[(58 + ch) * 68 + w] = sy;
    }

    // ================= GEMM1: perc(88->96) x w1t -> h1[256] =================
    // 8 outs x 2 pixel-pairs per thread; weights staged in smem, read as float4
    {
        u64 acc[8][2];
#pragma unroll
        for (int c = 0; c < 8; c++) { acc[c][0] = 0ull; acc[c][1] = 0ull; }

        for (int kk = 0; kk < 96; kk += 32) {
            __syncthreads();
            {
                const float4* src = reinterpret_cast<const float4*>(g_w1t + kk * 256);
                float4* dst = reinterpret_cast<float4*>(wbuf);
#pragma unroll
                for (int i = 0; i < 4; i++) dst[tid + NT * i] = src[tid + NT * i];
            }
            __syncthreads();
#pragma unroll
            for (int j = 0; j < 32; j++) {
                const ulonglong2 pv = *reinterpret_cast<const ulonglong2*>(
                    &percs[(kk + j) * 68 + (tx << 2)]);
                const float4* wr4 = reinterpret_cast<const float4*>(
                    &wbuf[j * 256 + (ty << 3)]);
                float4 wq0 = wr4[0], wq1 = wr4[1];
                u64 wv[8];
                wv[0] = bcast2(wq0.x); wv[1] = bcast2(wq0.y);
                wv[2] = bcast2(wq0.z); wv[3] = bcast2(wq0.w);
                wv[4] = bcast2(wq1.x); wv[5] = bcast2(wq1.y);
                wv[6] = bcast2(wq1.z); wv[7] = bcast2(wq1.w);
#pragma unroll
                for (int c = 0; c < 8; c++) {
                    acc[c][0] = ffma2(wv[c], pv.x, acc[c][0]);
                    acc[c][1] = ffma2(wv[c], pv.y, acc[c][1]);
                }
            }
        }
#pragma unroll
        for (int c = 0; c < 8; c++) {
            int o = (ty << 3) + c;
            float bb = b1[o];
            float a0, a1, a2, a3;
            unpack2(acc[c][0], a0, a1);
            unpack2(acc[c][1], a2, a3);
            float4 v;
            v.x = lk(a0 + bb);
            v.y = lk(a1 + bb);
            v.z = lk(a2 + bb);
            v.w = lk(a3 + bb);
            *reinterpret_cast<float4*>(&h1s[o * 68 + (tx << 2)]) = v;
        }
    }

    // ================= GEMM2: h1[256] x w2t -> h2[128] =================
    {
        u64 acc[4][2];
#pragma unroll
        for (int c = 0; c < 4; c++) { acc[c][0] = 0ull; acc[c][1] = 0ull; }

        for (int kk = 0; kk < 256; kk += 32) {
            __syncthreads();
            {
                const float4* src = reinterpret_cast<const float4*>(g_w2t + kk * 128);
                float4* dst = reinterpret_cast<float4*>(wbuf);
#pragma unroll
                for (int i = 0; i < 2; i++) dst[tid + NT * i] = src[tid + NT * i];
            }
            __syncthreads();
#pragma unroll
            for (int j = 0; j < 32; j++) {
                const ulonglong2 pv = *reinterpret_cast<const ulonglong2*>(
                    &h1s[(kk + j) * 68 + (tx << 2)]);
                const float4 wq0 = *reinterpret_cast<const float4*>(
                    &wbuf[j * 128 + (ty << 2)]);
                u64 wv[4];
                wv[0] = bcast2(wq0.x); wv[1] = bcast2(wq0.y);
                wv[2] = bcast2(wq0.z); wv[3] = bcast2(wq0.w);
#pragma unroll
                for (int c = 0; c < 4; c++) {
                    acc[c][0] = ffma2(wv[c], pv.x, acc[c][0]);
                    acc[c][1] = ffma2(wv[c], pv.y, acc[c][1]);
                }
            }
        }
#pragma unroll
        for (int c = 0; c < 4; c++) {
            int o = (ty << 2) + c;
            float a0, a1, a2, a3;
            unpack2(acc[c][0], a0, a1);
            unpack2(acc[c][1], a2, a3);
            float4 v;
            v.x = lk(a0);
            v.y = lk(a1);
            v.z = lk(a2);
            v.w = lk(a3);
            *reinterpret_cast<float4*>(&h2s[o * 68 + (tx << 2)]) = v;
        }
    }

    // ================= GEMM3: h2[128] x w3t -> dx[29..32] + update =========
    {
        u64 acc[2];
        acc[0] = 0ull; acc[1] = 0ull;

        for (int kk = 0; kk < 128; kk += 32) {
            __syncthreads();
            {
                const float4* src = reinterpret_cast<const float4*>(g_w3t + kk * 32);
                float4* dst = reinterpret_cast<float4*>(wbuf);
                if (tid < 256) dst[tid] = src[tid];
            }
            __syncthreads();
#pragma unroll
            for (int j = 0; j < 32; j++) {
                const ulonglong2 pv = *reinterpret_cast<const ulonglong2*>(
                    &h2s[(kk + j) * 68 + (tx << 2)]);
                u64 w0 = bcast2(wbuf[j * 32 + ty]);
                acc[0] = ffma2(w0, pv.x, acc[0]);
                acc[1] = ffma2(w0, pv.y, acc[1]);
            }
        }
        {
            int ch = ty;                       // 0..31
            if (ch < NCC) {
                float d0, d1, d2, d3;
                unpack2(acc[0], d0, d1);
                unpack2(acc[1], d2, d3);
                float dv[4] = {d0, d1, d2, d3};
#pragma unroll
                for (int p = 0; p < 4; p++) {
                    int w = (tx << 2) + p;
                    float inv = base_in[ch * PIX + w];
                    float outv;
                    if (ch < NIMG) outv = inv;                       // chan_mask = 0
                    else           outv = inv + dv[p] * fires[w];
                    base_out[ch * PIX + w] = outv;
                }
            }
        }
    }
}

// ---------------- readout: mean over HxW of class channels, softmax --------
__global__ void nca_reduce(float* __restrict__ out) {
    __shared__ float red[256];
    __shared__ float logit[NOUT];
    int b = blockIdx.x;
    int tid = threadIdx.x;
    for (int ch = 0; ch < NOUT; ch++) {
        float s = 0.0f;
        const float* src = g_bufA + ((long long)b * NCC + (NIMG + NHID + ch)) * PIX;
        for (int p = tid; p < PIX; p += 256) s += src[p];
        red[tid] = s;
        __syncthreads();
        for (int off = 128; off > 0; off >>= 1) {
            if (tid < off) red[tid] += red[tid + off];
            __syncthreads();
        }
        if (tid == 0) logit[ch] = red[0] * (1.0f / 4096.0f);
        __syncthreads();
    }
    if (tid == 0) {
        float m = -1e30f;
        for (int c = 0; c < NOUT; c++) m = fmaxf(m, logit[c]);
        float e[NOUT], sum = 0.0f;
        for (int c = 0; c < NOUT; c++) { e[c] = expf(logit[c] - m); sum += e[c]; }
        float inv = 1.0f / sum;
        for (int c = 0; c < NOUT; c++) out[b * NOUT + c] = e[c] * inv;
    }
}

// ---------------- launch ----------------
extern "C" void kernel_launch(void* const* d_in, const int* in_sizes, int n_in,
                              void* d_out, int out_size) {
    const float* x  = (const float*)d_in[0];
    const float* w1 = (const float*)d_in[1];
    const float* b1 = (const float*)d_in[2];
    const float* w2 = (const float*)d_in[3];
    const float* w3 = (const float*)d_in[4];
    const int* steps_p = (n_in > 5) ? (const int*)d_in[5] : nullptr;

    cudaFuncSetAttribute(nca_step, cudaFuncAttributeMaxDynamicSharedMemorySize,
                         SMEM_BYTES);

    // weight transpose + padding
    nca_prep<<<(96 * 256 + 256 * 128 + 128 * 32 + 255) / 256, 256>>>(w1, w2, w3);
    // state init (x | hid | zeros) into bufA
    {
        long long N = (long long)B_ * NCC * PIX;
        nca_init<<<(int)((N + 255) / 256), 256>>>(x);
    }
    // 20 fixed step launches, double buffered (device-side guard on steps)
    for (int s = 0; s < 20; s++) {
        nca_step<<<B_ * HW_, NT, SMEM_BYTES>>>(s & 1, s, steps_p, b1);
    }
    // readout
    nca_reduce<<<B_, 256>>>((float*)d_out);
    (void)in_sizes; (void)out_size;
}

// round 13
// speedup vs baseline: 2.0334x; 2.0334x over previous
#include <cuda_runtime.h>
#include <cstdint>

// ---------------- problem constants ----------------
#define NCC   29
#define NIMG  3
#define NHID  16
#define NOUT  10
#define B_    16
#define HW_   64
#define PIX   4096           // 64*64
#define INVEC 88             // 3*29+1
#define NT    256

typedef unsigned long long u64;

// ---------------- packed f32x2 helpers (bit-exact vs scalar FP32) ----------
__device__ __forceinline__ u64 bcast2(float a) {
    u64 r; asm("mov.b64 %0, {%1, %1};" : "=l"(r) : "f"(a)); return r;
}
__device__ __forceinline__ void unpack2(u64 v, float& a, float& b) {
    asm("mov.b64 {%0, %1}, %2;" : "=f"(a), "=f"(b) : "l"(v));
}
__device__ __forceinline__ u64 ffma2(u64 a, u64 b, u64 c) {
    u64 d; asm("fma.rn.f32x2 %0, %1, %2, %3;" : "=l"(d) : "l"(a), "l"(b), "l"(c));
    return d;
}

// ---------------- cp.async helpers ----------------
__device__ __forceinline__ void cpa16(uint32_t dst, const void* src) {
    asm volatile("cp.async.ca.shared.global [%0], [%1], 16;" :: "r"(dst), "l"(src));
}
#define CP_COMMIT() asm volatile("cp.async.commit_group;" ::: "memory")
#define CP_WAIT0()  asm volatile("cp.async.wait_group 0;" ::: "memory")

// ---------------- persistent device buffers (no allocation allowed) ----------
__device__ float g_bufA[B_ * NCC * PIX];
__device__ float g_bufB[B_ * NCC * PIX];
__device__ float g_w1t[96 * 256];    // [k(pad 96)][o=256]
__device__ float g_w2t[256 * 128];   // [k=256][o=128]
__device__ float g_w3t[128 * 32];    // [k=128][o(pad 32)]

// ---------------- JAX threefry2x32 (bit exact) ----------------
__device__ __forceinline__ void tf2x32(unsigned k0, unsigned k1,
                                       unsigned x0, unsigned x1,
                                       unsigned& o0, unsigned& o1) {
    unsigned ks2 = k0 ^ k1 ^ 0x1BD11BDAu;
    x0 += k0; x1 += k1;
#define TFR(r) { x0 += x1; x1 = (x1 << (r)) | (x1 >> (32 - (r))); x1 ^= x0; }
    TFR(13) TFR(15) TFR(26) TFR(6)
    x0 += k1;  x1 += ks2 + 1u;
    TFR(17) TFR(29) TFR(16) TFR(24)
    x0 += ks2; x1 += k0 + 2u;
    TFR(13) TFR(15) TFR(26) TFR(6)
    x0 += k0;  x1 += k1 + 3u;
    TFR(17) TFR(29) TFR(16) TFR(24)
    x0 += k1;  x1 += ks2 + 4u;
    TFR(13) TFR(15) TFR(26) TFR(6)
    x0 += ks2; x1 += k0 + 5u;
#undef TFR
    o0 = x0; o1 = x1;
}

// XLA ErfInv32 (Giles polynomials) — matches jax.random.normal
__device__ __forceinline__ float erfinv_xla(float x) {
    float w = -log1pf(-x * x);
    float p;
    if (w < 5.0f) {
        w -= 2.5f;
        p = 2.81022636e-08f;
        p = fmaf(p, w, 3.43273939e-07f);
        p = fmaf(p, w, -3.5233877e-06f);
        p = fmaf(p, w, -4.39150654e-06f);
        p = fmaf(p, w, 0.00021858087f);
        p = fmaf(p, w, -0.00125372503f);
        p = fmaf(p, w, -0.00417768164f);
        p = fmaf(p, w, 0.246640727f);
        p = fmaf(p, w, 1.50140941f);
    } else {
        w = sqrtf(w) - 3.0f;
        p = -0.000200214257f;
        p = fmaf(p, w, 0.000100950558f);
        p = fmaf(p, w, 0.00134934322f);
        p = fmaf(p, w, -0.00367342844f);
        p = fmaf(p, w, 0.00573950773f);
        p = fmaf(p, w, -0.0076224613f);
        p = fmaf(p, w, 0.00943887047f);
        p = fmaf(p, w, 1.00167406f);
        p = fmaf(p, w, 2.83297682f);
    }
    return p * x;
}

__device__ __forceinline__ float lk(float v) { return v >= 0.0f ? v : 0.01f * v; }

// u in [0,1) from raw bits, JAX convention
__device__ __forceinline__ float bits_to_unit(unsigned bits) {
    return __uint_as_float((bits >> 9) | 0x3f800000u) - 1.0f;
}

// ---------------- init kernel: state = [x | hid | zeros] ----------------
__global__ void nca_init(const float* __restrict__ x) {
    long long idx = (long long)blockIdx.x * blockDim.x + threadIdx.x;
    const long long N = (long long)B_ * NCC * PIX;
    if (idx >= N) return;
    int p  = (int)(idx & (PIX - 1));
    int ch = (int)((idx >> 12) % NCC);
    int b  = (int)(idx / ((long long)NCC * PIX));
    float v;
    if (ch < NIMG) {
        v = x[((long long)b * NIMG + ch) * PIX + p];
    } else if (ch < NIMG + NHID) {
        unsigned kh0, kh1;
        tf2x32(0u, 42u, 0u, 10000u, kh0, kh1);
        unsigned ih = ((unsigned)b * NHID + (unsigned)(ch - NIMG)) * PIX + (unsigned)p;
        const unsigned half = 524288u;
        unsigned c0, c1, o0, o1, bits;
        if (ih < half) { c0 = ih; c1 = ih + half; }
        else           { c0 = ih - half; c1 = ih; }
        tf2x32(kh0, kh1, c0, c1, o0, o1);
        bits = (ih < half) ? o0 : o1;
        float u = bits_to_unit(bits);
        const float lo = -0.99999994f;           // nextafterf(-1,0)
        float val = u * (1.0f - lo) + lo;
        val = fmaxf(lo, val);
        float nrm = 1.41421356237f * erfinv_xla(val);   // sqrt(2)*erfinv
        v = 0.5f + 0.225f * nrm;
    } else {
        v = 0.0f;
    }
    g_bufA[idx] = v;
}

// ---------------- weight transpose / pad kernel ----------------
__global__ void nca_prep(const float* __restrict__ w1,
                         const float* __restrict__ w2,
                         const float* __restrict__ w3) {
    int i = blockIdx.x * blockDim.x + threadIdx.x;
    if (i < 96 * 256) {
        int k = i >> 8, o = i & 255;
        g_w1t[i] = (k < INVEC) ? w1[o * INVEC + k] : 0.0f;
    } else if (i < 96 * 256 + 256 * 128) {
        int j = i - 96 * 256;
        int k = j >> 7, o = j & 127;
        g_w2t[j] = w2[o * 256 + k];
    } else if (i < 96 * 256 + 256 * 128 + 128 * 32) {
        int j = i - 96 * 256 - 256 * 128;
        int k = j >> 5, o = j & 31;
        g_w3t[j] = (o < NCC) ? w3[o * 128 + k] : 0.0f;
    }
}

// ---------------- shared memory layout (floats) ----------------
#define S_SROWS 0                 // 29*3*66 = 5742 -> pad 5744; w3buf aliases [0..4096)
#define S_PERCS 5744              // 96*68   = 6528
#define S_H1    12272             // 256*68  = 17408
#define S_H2    29680             // 128*68  = 8704
#define S_WBA   38384             // 8192
#define S_WBB   46576             // 8192
#define S_FIRE  54768             // 64
#define S_TOTAL 54832
#define SMEM_BYTES (S_TOTAL * 4)  // 219,328 bytes -> 1 CTA/SM

// ---------------- fused step kernel: one CTA per (b, row) ----------------
__global__ __launch_bounds__(NT, 1)
void nca_step(int parity, int step, const int* __restrict__ steps_p,
              const float* __restrict__ b1) {
    extern __shared__ float sm[];
    float* srows = sm + S_SROWS;
    float* w3buf = sm + S_SROWS;      // aliases srows (dead after perception)
    float* percs = sm + S_PERCS;
    float* h1s   = sm + S_H1;
    float* h2s   = sm + S_H2;
    float* wbA   = sm + S_WBA;
    float* wbB   = sm + S_WBB;
    float* fires = sm + S_FIRE;

    const int tid = threadIdx.x;
    const int bid = blockIdx.x;
    const int b = bid >> 6;
    const int h = bid & 63;
    const int tx = tid & 15;
    const int ty = tid >> 4;

    const float* sin_ = parity ? g_bufB : g_bufA;
    float*       sout = parity ? g_bufA : g_bufB;
    const float* base_in  = sin_ + ((long long)b * NCC) * PIX + h * 64;
    float*       base_out = sout + ((long long)b * NCC) * PIX + h * 64;

    const int S = steps_p ? steps_p[0] : 20;
    if (step >= S) {   // pass-through keeps double-buffer parity valid
        for (int i = tid; i < NCC * 64; i += NT) {
            int ch = i >> 6, w = i & 63;
            base_out[ch * PIX + w] = base_in[ch * PIX + w];
        }
        return;
    }

    // smem u32 addresses for cp.async
    const uint32_t uWBA = (uint32_t)__cvta_generic_to_shared(wbA);
    const uint32_t uWBB = (uint32_t)__cvta_generic_to_shared(wbB);
    const uint32_t uW3  = (uint32_t)__cvta_generic_to_shared(w3buf);

    // ---- PROLOGUE: issue weight chunk 0 (w1 kk=0 -> A); overlaps staging ----
    {
        const float4* src = reinterpret_cast<const float4*>(g_w1t);
#pragma unroll
        for (int i = 0; i < 8; i++)
            cpa16(uWBA + (tid + NT * i) * 16, src + tid + NT * i);
        CP_COMMIT();
    }

    // ---- stage 3 state rows (29ch x 3 x 66, zero-padded) ----
    for (int i = tid; i < NCC * 3 * 66; i += NT) {
        int ch = i / 198;
        int rem = i - ch * 198;
        int r = rem / 66;
        int c = rem - r * 66;
        int hh = h + r - 1;
        int ww = c - 1;
        float v = 0.0f;
        if (hh >= 0 && hh < 64 && ww >= 0 && ww < 64)
            v = sin_[((long long)b * NCC + ch) * PIX + hh * 64 + ww];
        srows[i] = v;
    }

    // ---- fire mask for this row (bit-exact JAX uniform < 0.5) ----
    if (tid < 64) {
        unsigned kf0, kf1;
        tf2x32(0u, 42u, 0u, (unsigned)step, kf0, kf1);   // fold_in(key(42), step)
        unsigned pix = ((unsigned)b * 64u + (unsigned)h) * 64u + (unsigned)tid;
        const unsigned half = 32768u;                    // n = 65536
        unsigned c0, c1, o0, o1;
        if (pix < half) { c0 = pix; c1 = pix + half; }
        else            { c0 = pix - half; c1 = pix; }
        tf2x32(kf0, kf1, c0, c1, o0, o1);
        unsigned bits = (pix < half) ? o0 : o1;
        float u = bits_to_unit(bits);
        fires[tid] = (u < 0.5f) ? 1.0f : 0.0f;
    }

    // ---- time channel + zero-pad rows 88..95 ----
    float tval = (float)step / 100.0f;
    if (tid < 68) percs[87 * 68 + tid] = (tid < 64) ? tval : 0.0f;
    for (int i = tid; i < 8 * 68; i += NT) percs[88 * 68 + i] = 0.0f;
    __syncthreads();                                     // B1: srows/percs staged

    // ---- perception: s, sobel-x, sobel-y ----
    for (int i = tid; i < NCC * 64; i += NT) {
        int ch = i >> 6, w = i & 63;
        const float* rp = srows + ch * 198;
        float tl = rp[w],       tc = rp[w + 1],       tr = rp[w + 2];
        float ml = rp[66 + w],                        mr = rp[66 + w + 2];
        float mc = rp[66 + w + 1];
        float bl = rp[132 + w], bc = rp[132 + w + 1], br = rp[132 + w + 2];
        float sx = ((tr - tl) + 2.0f * (mr - ml) + (br - bl)) * 0.125f;
        float sy = ((bl - tl) + 2.0f * (bc - tc) + (br - tr)) * 0.125f;
        percs[ch * 68 + w]        = mc;
        percs[(29 + ch) * 68 + w] = sx;
        percs[(58 + ch) * 68 + w] = sy;
    }

    // =====================================================================
    // 8-phase pipelined GEMM chain. Phase i: wait chunk i; sync; issue i+1;
    // compute i. Chunks: 0-2 = w1 (32k each), 3-6 = w2 (64k each), 7 = w3.
    // =====================================================================

    // ---------------- GEMM1: perc[96] x w1t -> h1[256] ----------------
    u64 acc1[16][2];
#pragma unroll
    for (int c = 0; c < 16; c++) { acc1[c][0] = 0ull; acc1[c][1] = 0ull; }

#pragma unroll
    for (int ph = 0; ph < 3; ph++) {
        CP_WAIT0();
        __syncthreads();
        // issue next chunk
        if (ph < 2) {            // w1 chunk ph+1 -> alternate buffer
            const float4* src = reinterpret_cast<const float4*>(
                g_w1t + (ph + 1) * 32 * 256);
            uint32_t dstb = (ph & 1) ? uWBA : uWBB;   // ph0->B, ph1->A
#pragma unroll
            for (int i = 0; i < 8; i++)
                cpa16(dstb + (tid + NT * i) * 16, src + tid + NT * i);
            CP_COMMIT();
        } else {                 // chunk 3 = w2 kk=0 -> B
            const float4* src = reinterpret_cast<const float4*>(g_w2t);
#pragma unroll
            for (int i = 0; i < 8; i++)
                cpa16(uWBB + (tid + NT * i) * 16, src + tid + NT * i);
            CP_COMMIT();
        }
        // compute chunk ph from buffer (ph even -> A, odd -> B)
        const float* wb = (ph & 1) ? wbB : wbA;
        const int kk = ph * 32;
#pragma unroll
        for (int j = 0; j < 32; j++) {
            const ulonglong2 pv = *reinterpret_cast<const ulonglong2*>(
                &percs[(kk + j) * 68 + (tx << 2)]);
            const float4* wr4 = reinterpret_cast<const float4*>(
                &wb[j * 256 + (ty << 4)]);
            float4 wq0 = wr4[0], wq1 = wr4[1], wq2 = wr4[2], wq3 = wr4[3];
            u64 wv[16];
            wv[0]  = bcast2(wq0.x); wv[1]  = bcast2(wq0.y);
            wv[2]  = bcast2(wq0.z); wv[3]  = bcast2(wq0.w);
            wv[4]  = bcast2(wq1.x); wv[5]  = bcast2(wq1.y);
            wv[6]  = bcast2(wq1.z); wv[7]  = bcast2(wq1.w);
            wv[8]  = bcast2(wq2.x); wv[9]  = bcast2(wq2.y);
            wv[10] = bcast2(wq2.z); wv[11] = bcast2(wq2.w);
            wv[12] = bcast2(wq3.x); wv[13] = bcast2(wq3.y);
            wv[14] = bcast2(wq3.z); wv[15] = bcast2(wq3.w);
#pragma unroll
            for (int c = 0; c < 16; c++) {
                acc1[c][0] = ffma2(wv[c], pv.x, acc1[c][0]);
                acc1[c][1] = ffma2(wv[c], pv.y, acc1[c][1]);
            }
        }
    }
    // GEMM1 epilogue -> h1s
#pragma unroll
    for (int c = 0; c < 16; c++) {
        int o = (ty << 4) + c;
        float bb = b1[o];
        float a0, a1, a2, a3;
        unpack2(acc1[c][0], a0, a1);
        unpack2(acc1[c][1], a2, a3);
        float4 v;
        v.x = lk(a0 + bb);
        v.y = lk(a1 + bb);
        v.z = lk(a2 + bb);
        v.w = lk(a3 + bb);
        *reinterpret_cast<float4*>(&h1s[o * 68 + (tx << 2)]) = v;
    }

    // ---------------- GEMM2: h1[256] x w2t -> h2[128] ----------------
    u64 acc2[8][2];
#pragma unroll
    for (int c = 0; c < 8; c++) { acc2[c][0] = 0ull; acc2[c][1] = 0ull; }

#pragma unroll
    for (int ph = 0; ph < 4; ph++) {           // chunks 3..6, 64 k each
        CP_WAIT0();
        __syncthreads();
        if (ph < 3) {            // w2 chunk ph+1 -> alternate buffer
            const float4* src = reinterpret_cast<const float4*>(
                g_w2t + (ph + 1) * 64 * 128);
            uint32_t dstb = (ph & 1) ? uWBB : uWBA;   // ph0->A, ph1->B, ph2->A
#pragma unroll
            for (int i = 0; i < 8; i++)
                cpa16(dstb + (tid + NT * i) * 16, src + tid + NT * i);
            CP_COMMIT();
        } else {                 // chunk 7 = w3 (whole) -> w3buf
            const float4* src = reinterpret_cast<const float4*>(g_w3t);
#pragma unroll
            for (int i = 0; i < 4; i++)
                cpa16(uW3 + (tid + NT * i) * 16, src + tid + NT * i);
            CP_COMMIT();
        }
        const float* wb = (ph & 1) ? wbA : wbB;  // ph0->B, ph1->A, ph2->B, ph3->A
        const int kk = ph * 64;
#pragma unroll 8
        for (int j = 0; j < 64; j++) {
            const ulonglong2 pv = *reinterpret_cast<const ulonglong2*>(
                &h1s[(kk + j) * 68 + (tx << 2)]);
            const float4* wr4 = reinterpret_cast<const float4*>(
                &wb[j * 128 + (ty << 3)]);
            float4 wq0 = wr4[0], wq1 = wr4[1];
            u64 wv[8];
            wv[0] = bcast2(wq0.x); wv[1] = bcast2(wq0.y);
            wv[2] = bcast2(wq0.z); wv[3] = bcast2(wq0.w);
            wv[4] = bcast2(wq1.x); wv[5] = bcast2(wq1.y);
            wv[6] = bcast2(wq1.z); wv[7] = bcast2(wq1.w);
#pragma unroll
            for (int c = 0; c < 8; c++) {
                acc2[c][0] = ffma2(wv[c], pv.x, acc2[c][0]);
                acc2[c][1] = ffma2(wv[c], pv.y, acc2[c][1]);
            }
        }
    }
    // GEMM2 epilogue -> h2s
#pragma unroll
    for (int c = 0; c < 8; c++) {
        int o = (ty << 3) + c;
        float a0, a1, a2, a3;
        unpack2(acc2[c][0], a0, a1);
        unpack2(acc2[c][1], a2, a3);
        float4 v;
        v.x = lk(a0);
        v.y = lk(a1);
        v.z = lk(a2);
        v.w = lk(a3);
        *reinterpret_cast<float4*>(&h2s[o * 68 + (tx << 2)]) = v;
    }

    // ---------------- GEMM3: h2[128] x w3t -> dx[29] + update --------------
    {
        CP_WAIT0();
        __syncthreads();        // h2s visible + w3buf resident

        u64 acc[2][2];
#pragma unroll
        for (int c = 0; c < 2; c++) { acc[c][0] = 0ull; acc[c][1] = 0ull; }

#pragma unroll 8
        for (int j = 0; j < 128; j++) {
            const ulonglong2 pv = *reinterpret_cast<const ulonglong2*>(
                &h2s[j * 68 + (tx << 2)]);
            const float2 wp = *reinterpret_cast<const float2*>(
                &w3buf[j * 32 + (ty << 1)]);
            u64 w0 = bcast2(wp.x);
            u64 w1v = bcast2(wp.y);
            acc[0][0] = ffma2(w0,  pv.x, acc[0][0]);
            acc[0][1] = ffma2(w0,  pv.y, acc[0][1]);
            acc[1][0] = ffma2(w1v, pv.x, acc[1][0]);
            acc[1][1] = ffma2(w1v, pv.y, acc[1][1]);
        }
#pragma unroll
        for (int c = 0; c < 2; c++) {
            int ch = (ty << 1) + c;
            if (ch < NCC) {
                float d0, d1, d2, d3;
                unpack2(acc[c][0], d0, d1);
                unpack2(acc[c][1], d2, d3);
                float dv[4] = {d0, d1, d2, d3};
#pragma unroll
                for (int p = 0; p < 4; p++) {
                    int w = (tx << 2) + p;
                    float inv = base_in[ch * PIX + w];
                    float outv;
                    if (ch < NIMG) outv = inv;                       // chan_mask = 0
                    else           outv = inv + dv[p] * fires[w];
                    base_out[ch * PIX + w] = outv;
                }
            }
        }
    }
}

// ---------------- readout: mean over HxW of class channels, softmax --------
__global__ void nca_reduce(float* __restrict__ out) {
    __shared__ float red[256];
    __shared__ float logit[NOUT];
    int b = blockIdx.x;
    int tid = threadIdx.x;
    for (int ch = 0; ch < NOUT; ch++) {
        float s = 0.0f;
        const float* src = g_bufA + ((long long)b * NCC + (NIMG + NHID + ch)) * PIX;
        for (int p = tid; p < PIX; p += 256) s += src[p];
        red[tid] = s;
        __syncthreads();
        for (int off = 128; off > 0; off >>= 1) {
            if (tid < off) red[tid] += red[tid + off];
            __syncthreads();
        }
        if (tid == 0) logit[ch] = red[0] * (1.0f / 4096.0f);
        __syncthreads();
    }
    if (tid == 0) {
        float m = -1e30f;
        for (int c = 0; c < NOUT; c++) m = fmaxf(m, logit[c]);
        float e[NOUT], sum = 0.0f;
        for (int c = 0; c < NOUT; c++) { e[c] = expf(logit[c] - m); sum += e[c]; }
        float inv = 1.0f / sum;
        for (int c = 0; c < NOUT; c++) out[b * NOUT + c] = e[c] * inv;
    }
}

// ---------------- launch ----------------
extern "C" void kernel_launch(void* const* d_in, const int* in_sizes, int n_in,
                              void* d_out, int out_size) {
    const float* x  = (const float*)d_in[0];
    const float* w1 = (const float*)d_in[1];
    const float* b1 = (const float*)d_in[2];
    const float* w2 = (const float*)d_in[3];
    const float* w3 = (const float*)d_in[4];
    const int* steps_p = (n_in > 5) ? (const int*)d_in[5] : nullptr;

    cudaFuncSetAttribute(nca_step, cudaFuncAttributeMaxDynamicSharedMemorySize,
                         SMEM_BYTES);

    // weight transpose + padding
    nca_prep<<<(96 * 256 + 256 * 128 + 128 * 32 + 255) / 256, 256>>>(w1, w2, w3);
    // state init (x | hid | zeros) into bufA
    {
        long long N = (long long)B_ * NCC * PIX;
        nca_init<<<(int)((N + 255) / 256), 256>>>(x);
    }
    // 20 fixed step launches, double buffered (device-side guard on steps)
    for (int s = 0; s < 20; s++) {
        nca_step<<<B_ * HW_, NT, SMEM_BYTES>>>(s & 1, s, steps_p, b1);
    }
    // readout
    nca_reduce<<<B_, 256>>>((float*)d_out);
    (void)in_sizes; (void)out_size;
}

// round 14
// speedup vs baseline: 2.4472x; 1.2035x over previous
#include <cuda_runtime.h>
#include <cstdint>

// ---------------- problem constants ----------------
#define NCC   29
#define NIMG  3
#define NHID  16
#define NOUT  10
#define B_    16
#define HW_   64
#define PIX   4096           // 64*64
#define INVEC 88             // 3*29+1
#define NT    256

typedef unsigned long long u64;

// ---------------- packed f32x2 helpers (bit-exact vs scalar FP32) ----------
__device__ __forceinline__ u64 bcast2(float a) {
    u64 r; asm("mov.b64 %0, {%1, %1};" : "=l"(r) : "f"(a)); return r;
}
__device__ __forceinline__ void unpack2(u64 v, float& a, float& b) {
    asm("mov.b64 {%0, %1}, %2;" : "=f"(a), "=f"(b) : "l"(v));
}
__device__ __forceinline__ u64 ffma2(u64 a, u64 b, u64 c) {
    u64 d; asm("fma.rn.f32x2 %0, %1, %2, %3;" : "=l"(d) : "l"(a), "l"(b), "l"(c));
    return d;
}

// ---------------- cp.async helpers ----------------
__device__ __forceinline__ void cpa16(uint32_t dst, const void* src) {
    asm volatile("cp.async.ca.shared.global [%0], [%1], 16;" :: "r"(dst), "l"(src));
}
#define CP_COMMIT() asm volatile("cp.async.commit_group;" ::: "memory")
#define CP_WAIT0()  asm volatile("cp.async.wait_group 0;" ::: "memory")

// ---------------- persistent device buffers (no allocation allowed) ----------
__device__ float g_bufA[B_ * NCC * PIX];
__device__ float g_bufB[B_ * NCC * PIX];
__device__ float g_w1t[96 * 256];    // [k(pad 96)][o=256]
__device__ float g_w2t[256 * 128];   // [k=256][o=128]
__device__ float g_w3t[128 * 32];    // [k=128][o(pad 32)]

// ---------------- JAX threefry2x32 (bit exact) ----------------
__device__ __forceinline__ void tf2x32(unsigned k0, unsigned k1,
                                       unsigned x0, unsigned x1,
                                       unsigned& o0, unsigned& o1) {
    unsigned ks2 = k0 ^ k1 ^ 0x1BD11BDAu;
    x0 += k0; x1 += k1;
#define TFR(r) { x0 += x1; x1 = (x1 << (r)) | (x1 >> (32 - (r))); x1 ^= x0; }
    TFR(13) TFR(15) TFR(26) TFR(6)
    x0 += k1;  x1 += ks2 + 1u;
    TFR(17) TFR(29) TFR(16) TFR(24)
    x0 += ks2; x1 += k0 + 2u;
    TFR(13) TFR(15) TFR(26) TFR(6)
    x0 += k0;  x1 += k1 + 3u;
    TFR(17) TFR(29) TFR(16) TFR(24)
    x0 += k1;  x1 += ks2 + 4u;
    TFR(13) TFR(15) TFR(26) TFR(6)
    x0 += ks2; x1 += k0 + 5u;
#undef TFR
    o0 = x0; o1 = x1;
}

// XLA ErfInv32 (Giles polynomials) — matches jax.random.normal
__device__ __forceinline__ float erfinv_xla(float x) {
    float w = -log1pf(-x * x);
    float p;
    if (w < 5.0f) {
        w -= 2.5f;
        p = 2.81022636e-08f;
        p = fmaf(p, w, 3.43273939e-07f);
        p = fmaf(p, w, -3.5233877e-06f);
        p = fmaf(p, w, -4.39150654e-06f);
        p = fmaf(p, w, 0.00021858087f);
        p = fmaf(p, w, -0.00125372503f);
        p = fmaf(p, w, -0.00417768164f);
        p = fmaf(p, w, 0.246640727f);
        p = fmaf(p, w, 1.50140941f);
    } else {
        w = sqrtf(w) - 3.0f;
        p = -0.000200214257f;
        p = fmaf(p, w, 0.000100950558f);
        p = fmaf(p, w, 0.00134934322f);
        p = fmaf(p, w, -0.00367342844f);
        p = fmaf(p, w, 0.00573950773f);
        p = fmaf(p, w, -0.0076224613f);
        p = fmaf(p, w, 0.00943887047f);
        p = fmaf(p, w, 1.00167406f);
        p = fmaf(p, w, 2.83297682f);
    }
    return p * x;
}

__device__ __forceinline__ float lk(float v) { return v >= 0.0f ? v : 0.01f * v; }

// u in [0,1) from raw bits, JAX convention
__device__ __forceinline__ float bits_to_unit(unsigned bits) {
    return __uint_as_float((bits >> 9) | 0x3f800000u) - 1.0f;
}

// ---------------- init kernel: state = [x | hid | zeros] ----------------
__global__ void nca_init(const float* __restrict__ x) {
    long long idx = (long long)blockIdx.x * blockDim.x + threadIdx.x;
    const long long N = (long long)B_ * NCC * PIX;
    if (idx >= N) return;
    int p  = (int)(idx & (PIX - 1));
    int ch = (int)((idx >> 12) % NCC);
    int b  = (int)(idx / ((long long)NCC * PIX));
    float v;
    if (ch < NIMG) {
        v = x[((long long)b * NIMG + ch) * PIX + p];
    } else if (ch < NIMG + NHID) {
        unsigned kh0, kh1;
        tf2x32(0u, 42u, 0u, 10000u, kh0, kh1);
        unsigned ih = ((unsigned)b * NHID + (unsigned)(ch - NIMG)) * PIX + (unsigned)p;
        const unsigned half = 524288u;
        unsigned c0, c1, o0, o1, bits;
        if (ih < half) { c0 = ih; c1 = ih + half; }
        else           { c0 = ih - half; c1 = ih; }
        tf2x32(kh0, kh1, c0, c1, o0, o1);
        bits = (ih < half) ? o0 : o1;
        float u = bits_to_unit(bits);
        const float lo = -0.99999994f;           // nextafterf(-1,0)
        float val = u * (1.0f - lo) + lo;
        val = fmaxf(lo, val);
        float nrm = 1.41421356237f * erfinv_xla(val);   // sqrt(2)*erfinv
        v = 0.5f + 0.225f * nrm;
    } else {
        v = 0.0f;
    }
    g_bufA[idx] = v;
}

// ---------------- weight transpose / pad kernel ----------------
__global__ void nca_prep(const float* __restrict__ w1,
                         const float* __restrict__ w2,
                         const float* __restrict__ w3) {
    int i = blockIdx.x * blockDim.x + threadIdx.x;
    if (i < 96 * 256) {
        int k = i >> 8, o = i & 255;
        g_w1t[i] = (k < INVEC) ? w1[o * INVEC + k] : 0.0f;
    } else if (i < 96 * 256 + 256 * 128) {
        int j = i - 96 * 256;
        int k = j >> 7, o = j & 127;
        g_w2t[j] = w2[o * 256 + k];
    } else if (i < 96 * 256 + 256 * 128 + 128 * 32) {
        int j = i - 96 * 256 - 256 * 128;
        int k = j >> 5, o = j & 31;
        g_w3t[j] = (o < NCC) ? w3[o * 128 + k] : 0.0f;
    }
}

// ---------------- shared memory layout (floats), stride 64 ----------------
// wbA  [0, 4096)           : chunk ping buffer (also w3 at the end)
// wbB  [4096, 8192)        : chunk pong buffer, aliases srows
// srows[4096, 9840)        : 29*3*66, dead after perception
// percs[9840, 15984)       : 96*64
// h1c  [15984, 24176)      : 128*64 chunk of h1; aliased by h2 after GEMM2
// fire [24176, 24240)
#define S_WBA   0
#define S_WBB   4096
#define S_SROWS 4096
#define S_PERCS 9840
#define S_H1C   15984
#define S_FIRE  24176
#define S_TOTAL 24240
#define SMEM_BYTES (S_TOTAL * 4)   // 96,960 bytes -> 2 CTAs/SM

// issue one 4096-float (16KB) weight chunk via cp.async (4 segs/thread)
__device__ __forceinline__ void issue_chunk(int c, uint32_t uA, uint32_t uB,
                                            int tid) {
    uint32_t dst = (c & 1) ? uB : uA;
    if (c < 3) {                       // w1 cols 0..127, rows c*32..+32
        int kk = c * 32;
#pragma unroll
        for (int i = 0; i < 4; i++) {
            int seg = tid + 256 * i;
            int row = seg >> 5, c16 = seg & 31;
            cpa16(dst + seg * 16, g_w1t + (kk + row) * 256 + c16 * 4);
        }
    } else if (c < 7) {                // w2 rows (c-3)*32..+32
        const float* src = g_w2t + (c - 3) * 32 * 128;
#pragma unroll
        for (int i = 0; i < 4; i++) {
            int seg = tid + 256 * i;
            cpa16(dst + seg * 16, src + seg * 4);
        }
    } else if (c < 10) {               // w1 cols 128..255, rows (c-7)*32..+32
        int kk = (c - 7) * 32;
#pragma unroll
        for (int i = 0; i < 4; i++) {
            int seg = tid + 256 * i;
            int row = seg >> 5, c16 = seg & 31;
            cpa16(dst + seg * 16, g_w1t + (kk + row) * 256 + 128 + c16 * 4);
        }
    } else if (c < 14) {               // w2 rows 128+(c-10)*32..+32
        const float* src = g_w2t + (128 + (c - 10) * 32) * 128;
#pragma unroll
        for (int i = 0; i < 4; i++) {
            int seg = tid + 256 * i;
            cpa16(dst + seg * 16, src + seg * 4);
        }
    } else {                           // w3 whole (4096 floats)
#pragma unroll
        for (int i = 0; i < 4; i++) {
            int seg = tid + 256 * i;
            cpa16(dst + seg * 16, g_w3t + seg * 4);
        }
    }
    CP_COMMIT();
}

// ---------------- fused step kernel: one CTA per (b, row) ----------------
__global__ __launch_bounds__(NT, 2)
void nca_step(int parity, int step, const int* __restrict__ steps_p,
              const float* __restrict__ b1) {
    extern __shared__ float sm[];
    float* wbA   = sm + S_WBA;
    float* wbB   = sm + S_WBB;
    float* srows = sm + S_SROWS;
    float* percs = sm + S_PERCS;
    float* h1c   = sm + S_H1C;
    float* h2s   = sm + S_H1C;        // h2 aliases h1c (after final GEMM2 read)
    float* fires = sm + S_FIRE;

    const int tid = threadIdx.x;
    const int bid = blockIdx.x;
    const int b = bid >> 6;
    const int h = bid & 63;
    const int tx = tid & 15;
    const int ty = tid >> 4;

    const float* sin_ = parity ? g_bufB : g_bufA;
    float*       sout = parity ? g_bufA : g_bufB;
    const float* base_in  = sin_ + ((long long)b * NCC) * PIX + h * 64;
    float*       base_out = sout + ((long long)b * NCC) * PIX + h * 64;

    const int S = steps_p ? steps_p[0] : 20;
    if (step >= S) {   // pass-through keeps double-buffer parity valid
        for (int i = tid; i < NCC * 64; i += NT) {
            int ch = i >> 6, w = i & 63;
            base_out[ch * PIX + w] = base_in[ch * PIX + w];
        }
        return;
    }

    const uint32_t uWBA = (uint32_t)__cvta_generic_to_shared(wbA);
    const uint32_t uWBB = (uint32_t)__cvta_generic_to_shared(wbB);

    // ---- PROLOGUE: issue chunk 0 (w1 C0 sub0 -> wbA; wbA never aliased) ----
    issue_chunk(0, uWBA, uWBB, tid);

    // ---- stage 3 state rows (29ch x 3 x 66, zero-padded) ----
    for (int i = tid; i < NCC * 3 * 66; i += NT) {
        int ch = i / 198;
        int rem = i - ch * 198;
        int r = rem / 66;
        int c = rem - r * 66;
        int hh = h + r - 1;
        int ww = c - 1;
        float v = 0.0f;
        if (hh >= 0 && hh < 64 && ww >= 0 && ww < 64)
            v = sin_[((long long)b * NCC + ch) * PIX + hh * 64 + ww];
        srows[i] = v;
    }

    // ---- fire mask for this row (bit-exact JAX uniform < 0.5) ----
    if (tid < 64) {
        unsigned kf0, kf1;
        tf2x32(0u, 42u, 0u, (unsigned)step, kf0, kf1);   // fold_in(key(42), step)
        unsigned pix = ((unsigned)b * 64u + (unsigned)h) * 64u + (unsigned)tid;
        const unsigned half = 32768u;                    // n = 65536
        unsigned c0, c1, o0, o1;
        if (pix < half) { c0 = pix; c1 = pix + half; }
        else            { c0 = pix - half; c1 = pix; }
        tf2x32(kf0, kf1, c0, c1, o0, o1);
        unsigned bits = (pix < half) ? o0 : o1;
        float u = bits_to_unit(bits);
        fires[tid] = (u < 0.5f) ? 1.0f : 0.0f;
    }

    // ---- time channel + zero rows 88..95 ----
    float tval = (float)step / 100.0f;
    if (tid < 64) percs[87 * 64 + tid] = tval;
    for (int i = tid; i < 8 * 64; i += NT) percs[88 * 64 + i] = 0.0f;
    __syncthreads();                                     // srows staged

    // ---- perception: s, sobel-x, sobel-y ----
    for (int i = tid; i < NCC * 64; i += NT) {
        int ch = i >> 6, w = i & 63;
        const float* rp = srows + ch * 198;
        float tl = rp[w],       tc = rp[w + 1],       tr = rp[w + 2];
        float ml = rp[66 + w],                        mr = rp[66 + w + 2];
        float mc = rp[66 + w + 1];
        float bl = rp[132 + w], bc = rp[132 + w + 1], br = rp[132 + w + 2];
        float sx = ((tr - tl) + 2.0f * (mr - ml) + (br - bl)) * 0.125f;
        float sy = ((bl - tl) + 2.0f * (bc - tc) + (br - tr)) * 0.125f;
        percs[ch * 64 + w]        = mc;
        percs[(29 + ch) * 64 + w] = sx;
        percs[(58 + ch) * 64 + w] = sy;
    }
    // NOTE: no sync here; the first phase's sync (below) orders percs/srows.

    // =====================================================================
    // 15-chunk pipeline. Phase p: WAIT chunk p; sync; issue p+1; compute p.
    // chunks 0-2: GEMM1 half0 | 3-6: GEMM2 part0 | 7-9: GEMM1 half1 |
    // 10-13: GEMM2 part1 | 14: GEMM3 weights.
    // =====================================================================

    u64 acc2[8][2];
#pragma unroll
    for (int c = 0; c < 8; c++) { acc2[c][0] = 0ull; acc2[c][1] = 0ull; }

    // ---------- GEMM1 macro body: 8 outs x 2 pairs, 32 k ----------
#define G1_BODY(WB, KK, ACC)                                                   \
    _Pragma("unroll")                                                          \
    for (int j = 0; j < 32; j++) {                                             \
        const ulonglong2 pv = *reinterpret_cast<const ulonglong2*>(            \
            &percs[(KK + j) * 64 + (tx << 2)]);                                \
        const float4* wr4 = reinterpret_cast<const float4*>(                   \
            &(WB)[j * 128 + (ty << 3)]);                                       \
        float4 wq0 = wr4[0], wq1 = wr4[1];                                     \
        u64 wv[8];                                                             \
        wv[0] = bcast2(wq0.x); wv[1] = bcast2(wq0.y);                          \
        wv[2] = bcast2(wq0.z); wv[3] = bcast2(wq0.w);                          \
        wv[4] = bcast2(wq1.x); wv[5] = bcast2(wq1.y);                          \
        wv[6] = bcast2(wq1.z); wv[7] = bcast2(wq1.w);                          \
        _Pragma("unroll")                                                      \
        for (int c = 0; c < 8; c++) {                                          \
            ACC[c][0] = ffma2(wv[c], pv.x, ACC[c][0]);                         \
            ACC[c][1] = ffma2(wv[c], pv.y, ACC[c][1]);                         \
        }                                                                      \
    }

    // ---------- GEMM2 macro body: 8 outs x 2 pairs, 32 k from h1c ----------
#define G2_BODY(WB, J0)                                                        \
    _Pragma("unroll")                                                          \
    for (int j = 0; j < 32; j++) {                                             \
        const ulonglong2 pv = *reinterpret_cast<const ulonglong2*>(            \
            &h1c[(J0 + j) * 64 + (tx << 2)]);                                  \
        const float4* wr4 = reinterpret_cast<const float4*>(                   \
            &(WB)[j * 128 + (ty << 3)]);                                       \
        float4 wq0 = wr4[0], wq1 = wr4[1];                                     \
        u64 wv[8];                                                             \
        wv[0] = bcast2(wq0.x); wv[1] = bcast2(wq0.y);                          \
        wv[2] = bcast2(wq0.z); wv[3] = bcast2(wq0.w);                          \
        wv[4] = bcast2(wq1.x); wv[5] = bcast2(wq1.y);                          \
        wv[6] = bcast2(wq1.z); wv[7] = bcast2(wq1.w);                          \
        _Pragma("unroll")                                                      \
        for (int c = 0; c < 8; c++) {                                          \
            acc2[c][0] = ffma2(wv[c], pv.x, acc2[c][0]);                       \
            acc2[c][1] = ffma2(wv[c], pv.y, acc2[c][1]);                       \
        }                                                                      \
    }

    // ---------------- GEMM1 half 0 (outs 0..127): phases 0..2 ----------------
    {
        u64 acc1[8][2];
#pragma unroll
        for (int c = 0; c < 8; c++) { acc1[c][0] = 0ull; acc1[c][1] = 0ull; }
#pragma unroll
        for (int ph = 0; ph < 3; ph++) {
            CP_WAIT0();
            __syncthreads();
            issue_chunk(ph + 1, uWBA, uWBB, tid);
            const float* wb = (ph & 1) ? wbB : wbA;      // chunk ph parity
            G1_BODY(wb, ph * 32, acc1)
        }
        // epilogue -> h1c (next phase's sync publishes it before GEMM2 reads)
#pragma unroll
        for (int c = 0; c < 8; c++) {
            int ol = (ty << 3) + c;                      // 0..127
            float bb = b1[ol];
            float a0, a1, a2, a3;
            unpack2(acc1[c][0], a0, a1);
            unpack2(acc1[c][1], a2, a3);
            float4 v;
            v.x = lk(a0 + bb);
            v.y = lk(a1 + bb);
            v.z = lk(a2 + bb);
            v.w = lk(a3 + bb);
            *reinterpret_cast<float4*>(&h1c[ol * 64 + (tx << 2)]) = v;
        }
    }

    // ---------------- GEMM2 part 0 (k 0..127): phases 3..6 ----------------
#pragma unroll
    for (int ph = 0; ph < 4; ph++) {
        CP_WAIT0();
        __syncthreads();
        issue_chunk(ph + 4, uWBA, uWBB, tid);
        const float* wb = ((ph + 3) & 1) ? wbB : wbA;
        G2_BODY(wb, ph * 32)
    }

    // ---------------- GEMM1 half 1 (outs 128..255): phases 7..9 -------------
    {
        u64 acc1[8][2];
#pragma unroll
        for (int c = 0; c < 8; c++) { acc1[c][0] = 0ull; acc1[c][1] = 0ull; }
#pragma unroll
        for (int ph = 0; ph < 3; ph++) {
            CP_WAIT0();
            __syncthreads();
            issue_chunk(ph + 8, uWBA, uWBB, tid);
            const float* wb = ((ph + 7) & 1) ? wbB : wbA;
            G1_BODY(wb, ph * 32, acc1)
        }
#pragma unroll
        for (int c = 0; c < 8; c++) {
            int ol = (ty << 3) + c;                      // local 0..127
            float bb = b1[128 + ol];
            float a0, a1, a2, a3;
            unpack2(acc1[c][0], a0, a1);
            unpack2(acc1[c][1], a2, a3);
            float4 v;
            v.x = lk(a0 + bb);
            v.y = lk(a1 + bb);
            v.z = lk(a2 + bb);
            v.w = lk(a3 + bb);
            *reinterpret_cast<float4*>(&h1c[ol * 64 + (tx << 2)]) = v;
        }
    }

    // ---------------- GEMM2 part 1 (k 128..255): phases 10..13 --------------
#pragma unroll
    for (int ph = 0; ph < 4; ph++) {
        CP_WAIT0();
        __syncthreads();
        issue_chunk(ph + 11, uWBA, uWBB, tid);           // 11..14 (14 = w3)
        const float* wb = ((ph + 10) & 1) ? wbB : wbA;
        G2_BODY(wb, ph * 32)
    }

    // ---------------- GEMM2 epilogue: h2 overwrites h1c ----------------
    __syncthreads();            // all h1c reads done before overwrite
#pragma unroll
    for (int c = 0; c < 8; c++) {
        int o = (ty << 3) + c;
        float a0, a1, a2, a3;
        unpack2(acc2[c][0], a0, a1);
        unpack2(acc2[c][1], a2, a3);
        float4 v;
        v.x = lk(a0);
        v.y = lk(a1);
        v.z = lk(a2);
        v.w = lk(a3);
        *reinterpret_cast<float4*>(&h2s[o * 64 + (tx << 2)]) = v;
    }
    CP_WAIT0();                 // w3 chunk (14 -> wbA) resident
    __syncthreads();            // h2 visible

    // ---------------- GEMM3: h2[128] x w3 -> dx[29] + update ----------------
    {
        u64 acc[2][2];
#pragma unroll
        for (int c = 0; c < 2; c++) { acc[c][0] = 0ull; acc[c][1] = 0ull; }

#pragma unroll 8
        for (int j = 0; j < 128; j++) {
            const ulonglong2 pv = *reinterpret_cast<const ulonglong2*>(
                &h2s[j * 64 + (tx << 2)]);
            const float2 wp = *reinterpret_cast<const float2*>(
                &wbA[j * 32 + (ty << 1)]);
            u64 w0 = bcast2(wp.x);
            u64 w1v = bcast2(wp.y);
            acc[0][0] = ffma2(w0,  pv.x, acc[0][0]);
            acc[0][1] = ffma2(w0,  pv.y, acc[0][1]);
            acc[1][0] = ffma2(w1v, pv.x, acc[1][0]);
            acc[1][1] = ffma2(w1v, pv.y, acc[1][1]);
        }
#pragma unroll
        for (int c = 0; c < 2; c++) {
            int ch = (ty << 1) + c;
            if (ch < NCC) {
                float d0, d1, d2, d3;
                unpack2(acc[c][0], d0, d1);
                unpack2(acc[c][1], d2, d3);
                float dv[4] = {d0, d1, d2, d3};
#pragma unroll
                for (int p = 0; p < 4; p++) {
                    int w = (tx << 2) + p;
                    float inv = base_in[ch * PIX + w];
                    float outv;
                    if (ch < NIMG) outv = inv;                       // chan_mask = 0
                    else           outv = inv + dv[p] * fires[w];
                    base_out[ch * PIX + w] = outv;
                }
            }
        }
    }
#undef G1_BODY
#undef G2_BODY
}

// ---------------- readout: mean over HxW of class channels, softmax --------
__global__ void nca_reduce(float* __restrict__ out) {
    __shared__ float red[256];
    __shared__ float logit[NOUT];
    int b = blockIdx.x;
    int tid = threadIdx.x;
    for (int ch = 0; ch < NOUT; ch++) {
        float s = 0.0f;
        const float* src = g_bufA + ((long long)b * NCC + (NIMG + NHID + ch)) * PIX;
        for (int p = tid; p < PIX; p += 256) s += src[p];
        red[tid] = s;
        __syncthreads();
        for (int off = 128; off > 0; off >>= 1) {
            if (tid < off) red[tid] += red[tid + off];
            __syncthreads();
        }
        if (tid == 0) logit[ch] = red[0] * (1.0f / 4096.0f);
        __syncthreads();
    }
    if (tid == 0) {
        float m = -1e30f;
        for (int c = 0; c < NOUT; c++) m = fmaxf(m, logit[c]);
        float e[NOUT], sum = 0.0f;
        for (int c = 0; c < NOUT; c++) { e[c] = expf(logit[c] - m); sum += e[c]; }
        float inv = 1.0f / sum;
        for (int c = 0; c < NOUT; c++) out[b * NOUT + c] = e[c] * inv;
    }
}

// ---------------- launch ----------------
extern "C" void kernel_launch(void* const* d_in, const int* in_sizes, int n_in,
                              void* d_out, int out_size) {
    const float* x  = (const float*)d_in[0];
    const float* w1 = (const float*)d_in[1];
    const float* b1 = (const float*)d_in[2];
    const float* w2 = (const float*)d_in[3];
    const float* w3 = (const float*)d_in[4];
    const int* steps_p = (n_in > 5) ? (const int*)d_in[5] : nullptr;

    cudaFuncSetAttribute(nca_step, cudaFuncAttributeMaxDynamicSharedMemorySize,
                         SMEM_BYTES);

    // weight transpose + padding
    nca_prep<<<(96 * 256 + 256 * 128 + 128 * 32 + 255) / 256, 256>>>(w1, w2, w3);
    // state init (x | hid | zeros) into bufA
    {
        long long N = (long long)B_ * NCC * PIX;
        nca_init<<<(int)((N + 255) / 256), 256>>>(x);
    }
    // 20 fixed step launches, double buffered (device-side guard on steps)
    for (int s = 0; s < 20; s++) {
        nca_step<<<B_ * HW_, NT, SMEM_BYTES>>>(s & 1, s, steps_p, b1);
    }
    // readout
    nca_reduce<<<B_, 256>>>((float*)d_out);
    (void)in_sizes; (void)out_size;
}